// round 2
// baseline (speedup 1.0000x reference)
#include <cuda_runtime.h>
#include <math.h>

#define S_MAX 20000
#define D_FIX 256

// Scratch (device globals: allocation-free per harness rules)
__device__ float g_pooled[S_MAX * D_FIX];   // [S, 256]
__device__ float g_sumg[S_MAX];             // [S]

// ---------------------------------------------------------------------------
// Kernel A: per-segment fused gate + weighted pooling.
// One CTA per segment, 256 threads (8 warps). index is sorted, so each
// segment is a contiguous node range found by binary search.
// Single sweep: e_i = w_i^p * exp(x_i.Wg + bg)   (max-shift cancels in e/Σe)
//   denom = Σ e_i ;  pooled = (Σ e_i x_i) / (denom + 1e-10)
// ---------------------------------------------------------------------------
__global__ void __launch_bounds__(256) seg_pool_kernel(
    const float* __restrict__ x,
    const float* __restrict__ weights,
    const float* __restrict__ Wg,
    const float* __restrict__ bg,
    const float* __restrict__ p_,
    const int*   __restrict__ index,
    int N)
{
    const int s = blockIdx.x;
    const int t = threadIdx.x;
    const int w = t >> 5;
    const int l = t & 31;

    // binary search: [start, end) = nodes with index == s
    int lo = 0, hi = N;
    while (lo < hi) { int mid = (lo + hi) >> 1; if (index[mid] <  s) lo = mid + 1; else hi = mid; }
    const int start = lo;
    hi = N;
    while (lo < hi) { int mid = (lo + hi) >> 1; if (index[mid] <= s) lo = mid + 1; else hi = mid; }
    const int end = lo;

    const float4* x4  = (const float4*)x;
    const float4* Wg4 = (const float4*)Wg;
    // lane l owns dims [4l..4l+3] and [128+4l..128+4l+3]
    const float4 wga = Wg4[l];
    const float4 wgb = Wg4[32 + l];
    const float bgv = bg[0];
    const float pv  = p_[0];

    float4 acc0 = make_float4(0.f, 0.f, 0.f, 0.f);
    float4 acc1 = make_float4(0.f, 0.f, 0.f, 0.f);
    float dsum = 0.f;

    for (int i = start + w; i < end; i += 8) {
        const float4* xr = x4 + (size_t)i * 64;
        const float4 xa = xr[l];
        const float4 xb = xr[32 + l];
        float pd = xa.x * wga.x + xa.y * wga.y + xa.z * wga.z + xa.w * wga.w
                 + xb.x * wgb.x + xb.y * wgb.y + xb.z * wgb.z + xb.w * wgb.w;
        #pragma unroll
        for (int off = 16; off; off >>= 1)
            pd += __shfl_xor_sync(0xffffffffu, pd, off);
        const float wv = weights[i];
        // e = w^p * exp(gate + bg) = exp(p*log(w) + gate + bg)
        const float e = expf(fmaf(pv, logf(wv), pd + bgv));
        dsum += e;
        acc0.x = fmaf(e, xa.x, acc0.x);
        acc0.y = fmaf(e, xa.y, acc0.y);
        acc0.z = fmaf(e, xa.z, acc0.z);
        acc0.w = fmaf(e, xa.w, acc0.w);
        acc1.x = fmaf(e, xb.x, acc1.x);
        acc1.y = fmaf(e, xb.y, acc1.y);
        acc1.z = fmaf(e, xb.z, acc1.z);
        acc1.w = fmaf(e, xb.w, acc1.w);
    }

    __shared__ float red[8 * 256];
    __shared__ float sred[8];
    ((float4*)(red + w * 256))[l]      = acc0;
    ((float4*)(red + w * 256))[32 + l] = acc1;
    if (l == 0) sred[w] = dsum;   // e identical across lanes after full reduce
    __syncthreads();

    float denom = 0.f;
    #pragma unroll
    for (int j = 0; j < 8; j++) denom += sred[j];
    float tot = 0.f;
    #pragma unroll
    for (int j = 0; j < 8; j++) tot += red[j * 256 + t];

    const float inv = 1.f / (denom + 1e-10f);
    g_pooled[(size_t)s * 256 + t] = tot * inv;
    if (t == 0) g_sumg[s] = denom * inv;
}

// ---------------------------------------------------------------------------
// Kernel B: out[S,256] = g_pooled @ Wm + sumg * bm  (fp32 SGEMM, FFMA2 path)
// BM=128, BN=64, BK=16, 256 threads, 8x4 micro-tile per thread.
// A tile stored in SMEM with each value DUPLICATED pairwise so the M operand
// of fma.rn.f32x2 is a {a,a} pair loaded directly (no per-use packing).
// ---------------------------------------------------------------------------
#define BMT 128
#define BNT 64
#define BKT 16

__device__ __forceinline__ void ffma2(unsigned long long& d,
                                      unsigned long long a,
                                      unsigned long long b) {
    asm("fma.rn.f32x2 %0, %1, %2, %0;" : "+l"(d) : "l"(a), "l"(b));
}

__global__ void __launch_bounds__(256) pooled_gemm_kernel(
    const float* __restrict__ Wm,
    const float* __restrict__ bmv_,
    float* __restrict__ out,
    int S)
{
    __shared__ float As2[BKT][2 * BMT];   // dup pairs: As2[k][2r]=As2[k][2r+1]=A[r][k]
    __shared__ float Bs[BKT][BNT];

    const int t = threadIdx.x;
    const int rowBase0 = blockIdx.x * BMT;
    const int colBase  = blockIdx.y * BNT;

    const int tm = t >> 4;        // 0..15
    const int tn = t & 15;        // 0..15
    const int rowOff = tm * 8;    // 8 rows per thread
    const int colOff = tn * 4;    // 4 cols per thread (2 f32x2 pairs)

    unsigned long long c[8][2];
    #pragma unroll
    for (int i = 0; i < 8; i++) { c[i][0] = 0ull; c[i][1] = 0ull; }

    for (int k0 = 0; k0 < 256; k0 += BKT) {
        // fill A tile (128 rows x 16 k): 2 float4 per thread, dup-stored
        #pragma unroll
        for (int j = 0; j < 2; j++) {
            const int idx = t + j * 256;
            const int r   = idx >> 2;       // 0..127
            const int c4  = idx & 3;        // 0..3 (float4 column within tile)
            const int grow = rowBase0 + r;
            float4 v = make_float4(0.f, 0.f, 0.f, 0.f);
            if (grow < S)
                v = *(const float4*)&g_pooled[(size_t)grow * 256 + k0 + c4 * 4];
            *(float2*)&As2[c4 * 4 + 0][2 * r] = make_float2(v.x, v.x);
            *(float2*)&As2[c4 * 4 + 1][2 * r] = make_float2(v.y, v.y);
            *(float2*)&As2[c4 * 4 + 2][2 * r] = make_float2(v.z, v.z);
            *(float2*)&As2[c4 * 4 + 3][2 * r] = make_float2(v.w, v.w);
        }
        // fill B tile (16 x 64): one float4 per thread
        {
            const int br  = t >> 4;   // 0..15
            const int bc4 = t & 15;   // 0..15
            *(float4*)&Bs[br][bc4 * 4] =
                *(const float4*)&Wm[(size_t)(k0 + br) * 256 + colBase + bc4 * 4];
        }
        __syncthreads();

        #pragma unroll
        for (int kk = 0; kk < BKT; kk++) {
            const ulonglong2* ar = (const ulonglong2*)&As2[kk][2 * rowOff];
            const ulonglong2 a01 = ar[0];
            const ulonglong2 a23 = ar[1];
            const ulonglong2 a45 = ar[2];
            const ulonglong2 a67 = ar[3];
            const ulonglong2 b = *(const ulonglong2*)&Bs[kk][colOff];
            ffma2(c[0][0], a01.x, b.x); ffma2(c[0][1], a01.x, b.y);
            ffma2(c[1][0], a01.y, b.x); ffma2(c[1][1], a01.y, b.y);
            ffma2(c[2][0], a23.x, b.x); ffma2(c[2][1], a23.x, b.y);
            ffma2(c[3][0], a23.y, b.x); ffma2(c[3][1], a23.y, b.y);
            ffma2(c[4][0], a45.x, b.x); ffma2(c[4][1], a45.x, b.y);
            ffma2(c[5][0], a45.y, b.x); ffma2(c[5][1], a45.y, b.y);
            ffma2(c[6][0], a67.x, b.x); ffma2(c[6][1], a67.x, b.y);
            ffma2(c[7][0], a67.y, b.x); ffma2(c[7][1], a67.y, b.y);
        }
        __syncthreads();
    }

    // epilogue: + sumg[row] * bm[col]
    const float4 bv = *(const float4*)&bmv_[colBase + colOff];
    #pragma unroll
    for (int i = 0; i < 8; i++) {
        const int row = rowBase0 + rowOff + i;
        if (row < S) {
            const float sg = g_sumg[row];
            float4 r;
            r.x = __uint_as_float((unsigned)(c[i][0] & 0xffffffffull)) + sg * bv.x;
            r.y = __uint_as_float((unsigned)(c[i][0] >> 32))           + sg * bv.y;
            r.z = __uint_as_float((unsigned)(c[i][1] & 0xffffffffull)) + sg * bv.z;
            r.w = __uint_as_float((unsigned)(c[i][1] >> 32))           + sg * bv.w;
            *(float4*)&out[(size_t)row * 256 + colBase + colOff] = r;
        }
    }
}

// ---------------------------------------------------------------------------
// inputs (metadata order): x, weights, Wg, bg, Wm, bm, p, index, [num_segments]
// ---------------------------------------------------------------------------
extern "C" void kernel_launch(void* const* d_in, const int* in_sizes, int n_in,
                              void* d_out, int out_size) {
    const float* x       = (const float*)d_in[0];
    const float* weights = (const float*)d_in[1];
    const float* Wg      = (const float*)d_in[2];
    const float* bg      = (const float*)d_in[3];
    const float* Wm      = (const float*)d_in[4];
    const float* bm      = (const float*)d_in[5];
    const float* p       = (const float*)d_in[6];
    const int*   index   = (const int*)d_in[7];

    const int N = in_sizes[7];
    const int D = in_sizes[2];            // 256
    int S = out_size / D;                 // 20000
    if (S > S_MAX) S = S_MAX;             // scratch capacity guard

    seg_pool_kernel<<<S, 256>>>(x, weights, Wg, bg, p, index, N);

    dim3 grid((S + BMT - 1) / BMT, D / BNT);
    pooled_gemm_kernel<<<grid, 256>>>(Wm, bm, (float*)d_out, S);
}

// round 4
// speedup vs baseline: 1.2097x; 1.2097x over previous
#include <cuda_runtime.h>
#include <math.h>

#define S_MAX 20000
#define D_FIX 256
#define CHUNK 96            // nodes per CTA in the pooling kernel
#define POOL_SMEM (CHUNK * 256 * 4 + CHUNK * 4 + (CHUNK + 1) * 4)

// Scratch (device globals: allocation-free per harness rules)
__device__ float g_pooled[S_MAX * D_FIX];   // raw Σ e_i x_i   [S, 256]
__device__ float g_denom[S_MAX];            // raw Σ e_i       [S]

// ---------------------------------------------------------------------------
// Kernel Z: zero the accumulators (graph replays re-use them).
// ---------------------------------------------------------------------------
__global__ void __launch_bounds__(256) zero_kernel() {
    const int i = blockIdx.x * 256 + threadIdx.x;
    const float4 z = make_float4(0.f, 0.f, 0.f, 0.f);
    if (i < S_MAX * (D_FIX / 4)) ((float4*)g_pooled)[i] = z;
    if (i < S_MAX / 4)           ((float4*)g_denom)[i]  = z;
}

// ---------------------------------------------------------------------------
// Kernel A: node-parallel fused gate + weighted pooling.
// Each CTA owns CHUNK contiguous nodes (index sorted => few segment
// boundaries per chunk). 3 phases:
//   1a: coalesced streaming copy of the x chunk into smem (max MLP)
//   1b: per-warp gate dots from smem; shuffle reduces deferred/batched
//   2 : thread-per-dim accumulate e*x with atomic flush at boundaries
// Sentinel idxs[len] = -1 ALWAYS, so the final partial accumulator is
// flushed even when a segment spans the chunk boundary (R3 bug).
// Max-shift cancels in e/Σe: e_i = exp(p*log(w_i) + x_i.Wg + bg).
// ---------------------------------------------------------------------------
__global__ void __launch_bounds__(256) node_pool_kernel(
    const float* __restrict__ x,
    const float* __restrict__ weights,
    const float* __restrict__ Wg,
    const float* __restrict__ bg,
    const float* __restrict__ p_,
    const int*   __restrict__ index,
    int N)
{
    extern __shared__ float smem[];
    float* xs  = smem;                          // [CHUNK * 256]
    float* es  = smem + CHUNK * 256;            // [CHUNK]
    int*   idxs = (int*)(es + CHUNK);           // [CHUNK + 1]

    const int base = blockIdx.x * CHUNK;
    const int len  = min(CHUNK, N - base);
    const int t = threadIdx.x;
    const int w = t >> 5;
    const int l = t & 31;

    // --- index staging; sentinel forces a final flush unconditionally ---
    if (t < len) idxs[t] = index[base + t];
    if (t == 0)  idxs[len] = -1;

    // --- phase 1a: coalesced streaming load x chunk -> smem ---
    {
        const float4* src = (const float4*)x + (size_t)base * 64;
        float4* dst = (float4*)xs;
        const int n4 = len * 64;
        #pragma unroll 4
        for (int i = t; i < n4; i += 256) dst[i] = __ldcs(src + i);
    }
    __syncthreads();

    // --- phase 1b: gate dots from smem, deferred reduces ---
    const float4* Wg4 = (const float4*)Wg;
    const float4 wga = Wg4[l];
    const float4 wgb = Wg4[32 + l];
    const float bgv = bg[0];
    const float pv  = p_[0];

    float pdv[12];
    float wv[12];
    const float4* xs4 = (const float4*)xs;
    #pragma unroll
    for (int jj = 0; jj < 12; jj++) {
        const int j = w + jj * 8;
        pdv[jj] = 0.f; wv[jj] = 1.f;
        if (j < len) {
            const float4 xa = xs4[j * 64 + l];
            const float4 xb = xs4[j * 64 + 32 + l];
            pdv[jj] = xa.x * wga.x + xa.y * wga.y + xa.z * wga.z + xa.w * wga.w
                    + xb.x * wgb.x + xb.y * wgb.y + xb.z * wgb.z + xb.w * wgb.w;
            wv[jj] = __ldg(&weights[base + j]);
        }
    }
    #pragma unroll
    for (int jj = 0; jj < 12; jj++) {
        float pd = pdv[jj];
        #pragma unroll
        for (int off = 16; off; off >>= 1)
            pd += __shfl_xor_sync(0xffffffffu, pd, off);
        pdv[jj] = pd;
    }
    #pragma unroll
    for (int jj = 0; jj < 12; jj++) {
        const int j = w + jj * 8;
        if (j < len && l == 0)
            es[j] = expf(fmaf(pv, logf(wv[jj]), pdv[jj] + bgv));
    }
    __syncthreads();

    // --- phase 2: thread-per-dim weighted accumulation + boundary flush ---
    {
        float acc = 0.f;
        int cur = idxs[0];
        for (int j = 0; j < len; j++) {
            acc = fmaf(es[j], xs[j * 256 + t], acc);
            const int nxt = idxs[j + 1];
            if (nxt != cur) {                      // uniform across CTA
                atomicAdd(&g_pooled[(size_t)cur * 256 + t], acc);
                acc = 0.f;
                cur = nxt;
            }
        }
    }
    // denominators (one thread; trivial serial tail, overlapped across CTAs)
    if (t == 0) {
        float d = 0.f;
        int cur = idxs[0];
        for (int j = 0; j < len; j++) {
            d += es[j];
            const int nxt = idxs[j + 1];
            if (nxt != cur) {
                atomicAdd(&g_denom[cur], d);
                d = 0.f;
                cur = nxt;
            }
        }
    }
}

// ---------------------------------------------------------------------------
// Kernel B: out = inv_denom * (g_pooled @ Wm) + (denom*inv_denom) * bm
// fp32 SGEMM, FFMA2 path. BM=128, BN=64, BK=16, 256 threads, 8x4 micro-tile.
// Normalization fused into the epilogue (GEMM is linear in rows).
// ---------------------------------------------------------------------------
#define BMT 128
#define BNT 64
#define BKT 16

__device__ __forceinline__ void ffma2(unsigned long long& d,
                                      unsigned long long a,
                                      unsigned long long b) {
    asm("fma.rn.f32x2 %0, %1, %2, %0;" : "+l"(d) : "l"(a), "l"(b));
}

__global__ void __launch_bounds__(256) pooled_gemm_kernel(
    const float* __restrict__ Wm,
    const float* __restrict__ bmv_,
    float* __restrict__ out,
    int S)
{
    __shared__ float As2[BKT][2 * BMT];   // dup pairs for f32x2 M-operand
    __shared__ float Bs[BKT][BNT];

    const int t = threadIdx.x;
    const int rowBase0 = blockIdx.x * BMT;
    const int colBase  = blockIdx.y * BNT;

    const int tm = t >> 4;
    const int tn = t & 15;
    const int rowOff = tm * 8;
    const int colOff = tn * 4;

    unsigned long long c[8][2];
    #pragma unroll
    for (int i = 0; i < 8; i++) { c[i][0] = 0ull; c[i][1] = 0ull; }

    for (int k0 = 0; k0 < 256; k0 += BKT) {
        #pragma unroll
        for (int j = 0; j < 2; j++) {
            const int idx = t + j * 256;
            const int r   = idx >> 2;
            const int c4  = idx & 3;
            const int grow = rowBase0 + r;
            float4 v = make_float4(0.f, 0.f, 0.f, 0.f);
            if (grow < S)
                v = *(const float4*)&g_pooled[(size_t)grow * 256 + k0 + c4 * 4];
            *(float2*)&As2[c4 * 4 + 0][2 * r] = make_float2(v.x, v.x);
            *(float2*)&As2[c4 * 4 + 1][2 * r] = make_float2(v.y, v.y);
            *(float2*)&As2[c4 * 4 + 2][2 * r] = make_float2(v.z, v.z);
            *(float2*)&As2[c4 * 4 + 3][2 * r] = make_float2(v.w, v.w);
        }
        {
            const int br  = t >> 4;
            const int bc4 = t & 15;
            *(float4*)&Bs[br][bc4 * 4] =
                *(const float4*)&Wm[(size_t)(k0 + br) * 256 + colBase + bc4 * 4];
        }
        __syncthreads();

        #pragma unroll
        for (int kk = 0; kk < BKT; kk++) {
            const ulonglong2* ar = (const ulonglong2*)&As2[kk][2 * rowOff];
            const ulonglong2 a01 = ar[0];
            const ulonglong2 a23 = ar[1];
            const ulonglong2 a45 = ar[2];
            const ulonglong2 a67 = ar[3];
            const ulonglong2 b = *(const ulonglong2*)&Bs[kk][colOff];
            ffma2(c[0][0], a01.x, b.x); ffma2(c[0][1], a01.x, b.y);
            ffma2(c[1][0], a01.y, b.x); ffma2(c[1][1], a01.y, b.y);
            ffma2(c[2][0], a23.x, b.x); ffma2(c[2][1], a23.x, b.y);
            ffma2(c[3][0], a23.y, b.x); ffma2(c[3][1], a23.y, b.y);
            ffma2(c[4][0], a45.x, b.x); ffma2(c[4][1], a45.x, b.y);
            ffma2(c[5][0], a45.y, b.x); ffma2(c[5][1], a45.y, b.y);
            ffma2(c[6][0], a67.x, b.x); ffma2(c[6][1], a67.x, b.y);
            ffma2(c[7][0], a67.y, b.x); ffma2(c[7][1], a67.y, b.y);
        }
        __syncthreads();
    }

    const float4 bv = *(const float4*)&bmv_[colBase + colOff];
    #pragma unroll
    for (int i = 0; i < 8; i++) {
        const int row = rowBase0 + rowOff + i;
        if (row < S) {
            const float d   = g_denom[row];
            const float inv = __fdividef(1.f, d + 1e-10f);
            const float sg  = d * inv;            // Σ gate  (≈1)
            float4 r;
            r.x = fmaf(__uint_as_float((unsigned)(c[i][0] & 0xffffffffull)), inv, sg * bv.x);
            r.y = fmaf(__uint_as_float((unsigned)(c[i][0] >> 32)),           inv, sg * bv.y);
            r.z = fmaf(__uint_as_float((unsigned)(c[i][1] & 0xffffffffull)), inv, sg * bv.z);
            r.w = fmaf(__uint_as_float((unsigned)(c[i][1] >> 32)),           inv, sg * bv.w);
            *(float4*)&out[(size_t)row * 256 + colBase + colOff] = r;
        }
    }
}

// ---------------------------------------------------------------------------
// inputs (metadata order): x, weights, Wg, bg, Wm, bm, p, index, [num_segments]
// ---------------------------------------------------------------------------
extern "C" void kernel_launch(void* const* d_in, const int* in_sizes, int n_in,
                              void* d_out, int out_size) {
    const float* x       = (const float*)d_in[0];
    const float* weights = (const float*)d_in[1];
    const float* Wg      = (const float*)d_in[2];
    const float* bg      = (const float*)d_in[3];
    const float* Wm      = (const float*)d_in[4];
    const float* bm      = (const float*)d_in[5];
    const float* p       = (const float*)d_in[6];
    const int*   index   = (const int*)d_in[7];

    const int N = in_sizes[7];
    const int D = in_sizes[2];            // 256
    int S = out_size / D;                 // 20000
    if (S > S_MAX) S = S_MAX;

    static int smem_set = 0;
    if (!smem_set) {
        cudaFuncSetAttribute(node_pool_kernel,
                             cudaFuncAttributeMaxDynamicSharedMemorySize, POOL_SMEM);
        smem_set = 1;
    }

    zero_kernel<<<(S_MAX * (D_FIX / 4) + 255) / 256, 256>>>();
    node_pool_kernel<<<(N + CHUNK - 1) / CHUNK, 256, POOL_SMEM>>>(
        x, weights, Wg, bg, p, index, N);
    dim3 grid((S + BMT - 1) / BMT, D / BNT);
    pooled_gemm_kernel<<<grid, 256>>>(Wm, bm, (float*)d_out, S);
}

// round 5
// speedup vs baseline: 1.5954x; 1.3188x over previous
#include <cuda_runtime.h>
#include <math.h>

#define S_MAX 20000
#define D_FIX 256
#define CHUNK 32            // nodes per CTA: smem = 33KB -> 6 CTAs/SM
#define POOL_SMEM (CHUNK * 256 * 4 + CHUNK * 4 + (CHUNK + 1) * 4)

// Scratch (device globals: allocation-free per harness rules)
__device__ float g_pooled[S_MAX * D_FIX];   // raw Σ e_i x_i   [S, 256]
__device__ float g_denom[S_MAX];            // raw Σ e_i       [S]

// ---------------------------------------------------------------------------
// Kernel Z: zero the accumulators (graph replays re-use them).
// ---------------------------------------------------------------------------
__global__ void __launch_bounds__(256) zero_kernel() {
    const int i = blockIdx.x * 256 + threadIdx.x;
    const float4 z = make_float4(0.f, 0.f, 0.f, 0.f);
    if (i < S_MAX * (D_FIX / 4)) ((float4*)g_pooled)[i] = z;
    if (i < S_MAX / 4)           ((float4*)g_denom)[i]  = z;
}

// ---------------------------------------------------------------------------
// Kernel A: node-parallel fused gate + weighted pooling.
// CHUNK contiguous nodes per CTA; 6 CTAs/SM phase-stagger so DRAM stays busy.
//   1a: coalesced streaming copy x chunk -> smem (pure LDG loop, max MLP)
//   1b: per-warp gate dots from smem; shuffle reduces batched after the loop
//   2 : thread-per-dim accumulate e*x, atomic flush at segment boundaries
// Sentinel idxs[len] = -1 always (forces final flush; cross-chunk segments
// are merged by the atomics).  e_i = exp(p*log(w_i) + x_i.Wg + bg); the
// segment-max shift cancels in e/Σe.
// ---------------------------------------------------------------------------
__global__ void __launch_bounds__(256) node_pool_kernel(
    const float* __restrict__ x,
    const float* __restrict__ weights,
    const float* __restrict__ Wg,
    const float* __restrict__ bg,
    const float* __restrict__ p_,
    const int*   __restrict__ index,
    int N)
{
    extern __shared__ float smem[];
    float* xs  = smem;                          // [CHUNK * 256]
    float* es  = smem + CHUNK * 256;            // [CHUNK]
    int*   idxs = (int*)(es + CHUNK);           // [CHUNK + 1]

    const int base = blockIdx.x * CHUNK;
    const int len  = min(CHUNK, N - base);
    const int t = threadIdx.x;
    const int w = t >> 5;
    const int l = t & 31;

    if (t < len) idxs[t] = index[base + t];
    if (t == 0)  idxs[len] = -1;

    // --- phase 1a: coalesced streaming load x chunk -> smem ---
    {
        const float4* src = (const float4*)x + (size_t)base * 64;
        float4* dst = (float4*)xs;
        const int n4 = len * 64;                // <= 2048
        #pragma unroll 8
        for (int i = t; i < n4; i += 256) dst[i] = __ldcs(src + i);
    }
    __syncthreads();

    // --- phase 1b: gate dots from smem, deferred reduces ---
    const float4* Wg4 = (const float4*)Wg;
    const float4 wga = Wg4[l];
    const float4 wgb = Wg4[32 + l];
    const float bgv = bg[0];
    const float pv  = p_[0];

    const int NJJ = CHUNK / 8;                  // nodes per warp
    float pdv[NJJ];
    float wv[NJJ];
    const float4* xs4 = (const float4*)xs;
    #pragma unroll
    for (int jj = 0; jj < NJJ; jj++) {
        const int j = w + jj * 8;
        pdv[jj] = 0.f; wv[jj] = 1.f;
        if (j < len) {
            const float4 xa = xs4[j * 64 + l];
            const float4 xb = xs4[j * 64 + 32 + l];
            pdv[jj] = xa.x * wga.x + xa.y * wga.y + xa.z * wga.z + xa.w * wga.w
                    + xb.x * wgb.x + xb.y * wgb.y + xb.z * wgb.z + xb.w * wgb.w;
            wv[jj] = __ldg(&weights[base + j]);
        }
    }
    #pragma unroll
    for (int jj = 0; jj < NJJ; jj++) {
        float pd = pdv[jj];
        #pragma unroll
        for (int off = 16; off; off >>= 1)
            pd += __shfl_xor_sync(0xffffffffu, pd, off);
        pdv[jj] = pd;
    }
    #pragma unroll
    for (int jj = 0; jj < NJJ; jj++) {
        const int j = w + jj * 8;
        if (j < len && l == 0)
            es[j] = expf(fmaf(pv, logf(wv[jj]), pdv[jj] + bgv));
    }
    __syncthreads();

    // --- phase 2: thread-per-dim weighted accumulation + boundary flush ---
    {
        float acc = 0.f;
        int cur = idxs[0];
        for (int j = 0; j < len; j++) {
            acc = fmaf(es[j], xs[j * 256 + t], acc);
            const int nxt = idxs[j + 1];
            if (nxt != cur) {                      // uniform across CTA
                atomicAdd(&g_pooled[(size_t)cur * 256 + t], acc);
                acc = 0.f;
                cur = nxt;
            }
        }
    }
    if (t == 0) {
        float d = 0.f;
        int cur = idxs[0];
        for (int j = 0; j < len; j++) {
            d += es[j];
            const int nxt = idxs[j + 1];
            if (nxt != cur) {
                atomicAdd(&g_denom[cur], d);
                d = 0.f;
                cur = nxt;
            }
        }
    }
}

// ---------------------------------------------------------------------------
// Kernel B: out = inv_denom * (g_pooled @ Wm) + (denom*inv_denom) * bm
// fp32 SGEMM, FFMA2 path, DOUBLE-BUFFERED smem (one sync per K-tile,
// global->reg prefetch issued before the compute of the current tile).
// BM=128, BN=64, BK=16, 256 threads, 8x4 micro-tile per thread.
// ---------------------------------------------------------------------------
#define BMT 128
#define BNT 64
#define BKT 16
#define NKT (256 / BKT)

__device__ __forceinline__ void ffma2(unsigned long long& d,
                                      unsigned long long a,
                                      unsigned long long b) {
    asm("fma.rn.f32x2 %0, %1, %2, %0;" : "+l"(d) : "l"(a), "l"(b));
}

__global__ void __launch_bounds__(256) pooled_gemm_kernel(
    const float* __restrict__ Wm,
    const float* __restrict__ bmv_,
    float* __restrict__ out,
    int S)
{
    __shared__ float As2[2][BKT][2 * BMT];   // dup pairs for f32x2 M-operand
    __shared__ float Bs[2][BKT][BNT];

    const int t = threadIdx.x;
    const int rowBase0 = blockIdx.x * BMT;
    const int colBase  = blockIdx.y * BNT;

    const int tm = t >> 4;
    const int tn = t & 15;
    const int rowOff = tm * 8;
    const int colOff = tn * 4;

    // hoisted fill coordinates
    const int ar  = t >> 2;          // A rows r and r+64, same c4
    const int ac4 = t & 3;
    const int grow0 = rowBase0 + ar;
    const int grow1 = rowBase0 + ar + 64;
    const int br  = t >> 4;          // B row 0..15
    const int bc4 = t & 15;

    unsigned long long c[8][2];
    #pragma unroll
    for (int i = 0; i < 8; i++) { c[i][0] = 0ull; c[i][1] = 0ull; }

    const float4 z4 = make_float4(0.f, 0.f, 0.f, 0.f);

    // prologue: load tile 0
    float4 va0 = z4, va1 = z4, vb;
    if (grow0 < S) va0 = *(const float4*)&g_pooled[(size_t)grow0 * 256 + ac4 * 4];
    if (grow1 < S) va1 = *(const float4*)&g_pooled[(size_t)grow1 * 256 + ac4 * 4];
    vb = *(const float4*)&Wm[(size_t)br * 256 + colBase + bc4 * 4];

    {
        float* a = &As2[0][ac4 * 4][0];
        *(float2*)&a[0 * 2 * BMT + 2 * ar] = make_float2(va0.x, va0.x);
        *(float2*)&a[1 * 2 * BMT + 2 * ar] = make_float2(va0.y, va0.y);
        *(float2*)&a[2 * 2 * BMT + 2 * ar] = make_float2(va0.z, va0.z);
        *(float2*)&a[3 * 2 * BMT + 2 * ar] = make_float2(va0.w, va0.w);
        *(float2*)&a[0 * 2 * BMT + 2 * (ar + 64)] = make_float2(va1.x, va1.x);
        *(float2*)&a[1 * 2 * BMT + 2 * (ar + 64)] = make_float2(va1.y, va1.y);
        *(float2*)&a[2 * 2 * BMT + 2 * (ar + 64)] = make_float2(va1.z, va1.z);
        *(float2*)&a[3 * 2 * BMT + 2 * (ar + 64)] = make_float2(va1.w, va1.w);
        *(float4*)&Bs[0][br][bc4 * 4] = vb;
    }
    __syncthreads();

    #pragma unroll 4
    for (int kt = 0; kt < NKT; kt++) {
        const int cur = kt & 1;
        const int nxt = cur ^ 1;

        // prefetch next tile (issue LDGs before the compute)
        float4 pa0 = z4, pa1 = z4, pb = z4;
        if (kt + 1 < NKT) {
            const int k0 = (kt + 1) * BKT;
            if (grow0 < S) pa0 = *(const float4*)&g_pooled[(size_t)grow0 * 256 + k0 + ac4 * 4];
            if (grow1 < S) pa1 = *(const float4*)&g_pooled[(size_t)grow1 * 256 + k0 + ac4 * 4];
            pb = *(const float4*)&Wm[(size_t)(k0 + br) * 256 + colBase + bc4 * 4];
        }

        // compute current tile
        #pragma unroll
        for (int kk = 0; kk < BKT; kk++) {
            const ulonglong2* arp = (const ulonglong2*)&As2[cur][kk][2 * rowOff];
            const ulonglong2 a01 = arp[0];
            const ulonglong2 a23 = arp[1];
            const ulonglong2 a45 = arp[2];
            const ulonglong2 a67 = arp[3];
            const ulonglong2 b = *(const ulonglong2*)&Bs[cur][kk][colOff];
            ffma2(c[0][0], a01.x, b.x); ffma2(c[0][1], a01.x, b.y);
            ffma2(c[1][0], a01.y, b.x); ffma2(c[1][1], a01.y, b.y);
            ffma2(c[2][0], a23.x, b.x); ffma2(c[2][1], a23.x, b.y);
            ffma2(c[3][0], a23.y, b.x); ffma2(c[3][1], a23.y, b.y);
            ffma2(c[4][0], a45.x, b.x); ffma2(c[4][1], a45.x, b.y);
            ffma2(c[5][0], a45.y, b.x); ffma2(c[5][1], a45.y, b.y);
            ffma2(c[6][0], a67.x, b.x); ffma2(c[6][1], a67.x, b.y);
            ffma2(c[7][0], a67.y, b.x); ffma2(c[7][1], a67.y, b.y);
        }

        // store prefetched tile into the other buffer
        if (kt + 1 < NKT) {
            float* a = &As2[nxt][ac4 * 4][0];
            *(float2*)&a[0 * 2 * BMT + 2 * ar] = make_float2(pa0.x, pa0.x);
            *(float2*)&a[1 * 2 * BMT + 2 * ar] = make_float2(pa0.y, pa0.y);
            *(float2*)&a[2 * 2 * BMT + 2 * ar] = make_float2(pa0.z, pa0.z);
            *(float2*)&a[3 * 2 * BMT + 2 * ar] = make_float2(pa0.w, pa0.w);
            *(float2*)&a[0 * 2 * BMT + 2 * (ar + 64)] = make_float2(pa1.x, pa1.x);
            *(float2*)&a[1 * 2 * BMT + 2 * (ar + 64)] = make_float2(pa1.y, pa1.y);
            *(float2*)&a[2 * 2 * BMT + 2 * (ar + 64)] = make_float2(pa1.z, pa1.z);
            *(float2*)&a[3 * 2 * BMT + 2 * (ar + 64)] = make_float2(pa1.w, pa1.w);
            *(float4*)&Bs[nxt][br][bc4 * 4] = pb;
            __syncthreads();
        }
    }

    // epilogue: normalization fused (GEMM is row-linear)
    const float4 bv = *(const float4*)&bmv_[colBase + colOff];
    #pragma unroll
    for (int i = 0; i < 8; i++) {
        const int row = rowBase0 + rowOff + i;
        if (row < S) {
            const float d   = g_denom[row];
            const float inv = __fdividef(1.f, d + 1e-10f);
            const float sg  = d * inv;            // Σ gate  (≈1)
            float4 r;
            r.x = fmaf(__uint_as_float((unsigned)(c[i][0] & 0xffffffffull)), inv, sg * bv.x);
            r.y = fmaf(__uint_as_float((unsigned)(c[i][0] >> 32)),           inv, sg * bv.y);
            r.z = fmaf(__uint_as_float((unsigned)(c[i][1] & 0xffffffffull)), inv, sg * bv.z);
            r.w = fmaf(__uint_as_float((unsigned)(c[i][1] >> 32)),           inv, sg * bv.w);
            *(float4*)&out[(size_t)row * 256 + colBase + colOff] = r;
        }
    }
}

// ---------------------------------------------------------------------------
// inputs (metadata order): x, weights, Wg, bg, Wm, bm, p, index, [num_segments]
// ---------------------------------------------------------------------------
extern "C" void kernel_launch(void* const* d_in, const int* in_sizes, int n_in,
                              void* d_out, int out_size) {
    const float* x       = (const float*)d_in[0];
    const float* weights = (const float*)d_in[1];
    const float* Wg      = (const float*)d_in[2];
    const float* bg      = (const float*)d_in[3];
    const float* Wm      = (const float*)d_in[4];
    const float* bm      = (const float*)d_in[5];
    const float* p       = (const float*)d_in[6];
    const int*   index   = (const int*)d_in[7];

    const int N = in_sizes[7];
    const int D = in_sizes[2];            // 256
    int S = out_size / D;                 // 20000
    if (S > S_MAX) S = S_MAX;

    zero_kernel<<<(S_MAX * (D_FIX / 4) + 255) / 256, 256>>>();
    node_pool_kernel<<<(N + CHUNK - 1) / CHUNK, 256, POOL_SMEM>>>(
        x, weights, Wg, bg, p, index, N);
    dim3 grid((S + BMT - 1) / BMT, D / BNT);
    pooled_gemm_kernel<<<grid, 256>>>(Wm, bm, (float*)d_out, S);
}

// round 9
// speedup vs baseline: 1.9499x; 1.2222x over previous
#include <cuda_runtime.h>
#include <cuda_bf16.h>
#include <cstdint>
#include <math.h>

typedef unsigned int       u32;
typedef unsigned long long u64;

#define S_MAX 20000
#define D_FIX 256
#define CHUNK 32
#define POOL_SMEM (CHUNK * 256 * 4 + CHUNK * 4 + (CHUNK + 1) * 4)

// Scratch (device globals: allocation-free per harness rules)
__device__ float g_pooled[S_MAX * D_FIX];       // raw Σ e_i x_i  [S,256]
__device__ float g_denom[S_MAX];                // raw Σ e_i      [S]
__device__ __nv_bfloat16 g_A2[S_MAX * 512];     // pooled bf16: [s][0:256)=hi, [256:512)=lo
__device__ __nv_bfloat16 g_Bhi[256 * 256];      // Wm^T hi  [n][k]
__device__ __nv_bfloat16 g_Blo[256 * 256];      // Wm^T lo  [n][k]

// single dynamic-smem symbol for the pool kernel
extern __shared__ char dyn_smem[];

__device__ __forceinline__ u32 pack_bf2(__nv_bfloat16 a, __nv_bfloat16 b) {
    return (u32)__bfloat16_as_ushort(a) | ((u32)__bfloat16_as_ushort(b) << 16);
}

// ===========================================================================
// Kernel Z: zero the accumulators
// ===========================================================================
__global__ void __launch_bounds__(256) zero_kernel() {
    const int i = blockIdx.x * 256 + threadIdx.x;
    const float4 z = make_float4(0.f, 0.f, 0.f, 0.f);
    if (i < S_MAX * (D_FIX / 4)) ((float4*)g_pooled)[i] = z;
    if (i < S_MAX / 4)           ((float4*)g_denom)[i]  = z;
}

// ===========================================================================
// Kernel P: split Wm^T into bf16 hi/lo  ([n][k], K-contiguous)
// ===========================================================================
__global__ void __launch_bounds__(256) prep_b_kernel(const float* __restrict__ Wm) {
    const int n = blockIdx.x;      // 0..255
    const int k = threadIdx.x;     // 0..255
    const float v = Wm[k * 256 + n];
    const __nv_bfloat16 hi = __float2bfloat16(v);
    const __nv_bfloat16 lo = __float2bfloat16(v - __bfloat162float(hi));
    g_Bhi[n * 256 + k] = hi;
    g_Blo[n * 256 + k] = lo;
}

// ===========================================================================
// Kernel A: node-parallel fused gate + weighted pooling (unchanged, passing)
// ===========================================================================
__global__ void __launch_bounds__(256) node_pool_kernel(
    const float* __restrict__ x,
    const float* __restrict__ weights,
    const float* __restrict__ Wg,
    const float* __restrict__ bg,
    const float* __restrict__ p_,
    const int*   __restrict__ index,
    int N)
{
    float* xs  = (float*)dyn_smem;
    float* es  = xs + CHUNK * 256;
    int*   idxs = (int*)(es + CHUNK);

    const int base = blockIdx.x * CHUNK;
    const int len  = min(CHUNK, N - base);
    const int t = threadIdx.x;
    const int w = t >> 5;
    const int l = t & 31;

    if (t < len) idxs[t] = index[base + t];
    if (t == 0)  idxs[len] = -1;

    {
        const float4* src = (const float4*)x + (size_t)base * 64;
        float4* dst = (float4*)xs;
        const int n4 = len * 64;
        #pragma unroll 8
        for (int i = t; i < n4; i += 256) dst[i] = __ldcs(src + i);
    }
    __syncthreads();

    const float4* Wg4 = (const float4*)Wg;
    const float4 wga = Wg4[l];
    const float4 wgb = Wg4[32 + l];
    const float bgv = bg[0];
    const float pv  = p_[0];

    const int NJJ = CHUNK / 8;
    float pdv[NJJ], wv[NJJ];
    const float4* xs4 = (const float4*)xs;
    #pragma unroll
    for (int jj = 0; jj < NJJ; jj++) {
        const int j = w + jj * 8;
        pdv[jj] = 0.f; wv[jj] = 1.f;
        if (j < len) {
            const float4 xa = xs4[j * 64 + l];
            const float4 xb = xs4[j * 64 + 32 + l];
            pdv[jj] = xa.x * wga.x + xa.y * wga.y + xa.z * wga.z + xa.w * wga.w
                    + xb.x * wgb.x + xb.y * wgb.y + xb.z * wgb.z + xb.w * wgb.w;
            wv[jj] = __ldg(&weights[base + j]);
        }
    }
    #pragma unroll
    for (int jj = 0; jj < NJJ; jj++) {
        float pd = pdv[jj];
        #pragma unroll
        for (int off = 16; off; off >>= 1)
            pd += __shfl_xor_sync(0xffffffffu, pd, off);
        pdv[jj] = pd;
    }
    #pragma unroll
    for (int jj = 0; jj < NJJ; jj++) {
        const int j = w + jj * 8;
        if (j < len && l == 0)
            es[j] = expf(fmaf(pv, logf(wv[jj]), pdv[jj] + bgv));
    }
    __syncthreads();

    {
        float acc = 0.f;
        int cur = idxs[0];
        for (int j = 0; j < len; j++) {
            acc = fmaf(es[j], xs[j * 256 + t], acc);
            const int nxt = idxs[j + 1];
            if (nxt != cur) {
                atomicAdd(&g_pooled[(size_t)cur * 256 + t], acc);
                acc = 0.f;
                cur = nxt;
            }
        }
    }
    if (t == 0) {
        float d = 0.f;
        int cur = idxs[0];
        for (int j = 0; j < len; j++) {
            d += es[j];
            const int nxt = idxs[j + 1];
            if (nxt != cur) {
                atomicAdd(&g_denom[cur], d);
                d = 0.f;
                cur = nxt;
            }
        }
    }
}

// ===========================================================================
// Kernel C: convert pooled fp32 -> bf16 hi|lo  (runs after pooling)
// ===========================================================================
__global__ void __launch_bounds__(256) convert_a_kernel(int S) {
    const int idx = blockIdx.x * 256 + threadIdx.x;   // over S*64 float4
    if (idx >= S * 64) return;
    const float4 v = ((const float4*)g_pooled)[idx];
    const int row = idx >> 6;
    const int c4  = idx & 63;
    const __nv_bfloat16 h0 = __float2bfloat16(v.x);
    const __nv_bfloat16 h1 = __float2bfloat16(v.y);
    const __nv_bfloat16 h2 = __float2bfloat16(v.z);
    const __nv_bfloat16 h3 = __float2bfloat16(v.w);
    const __nv_bfloat16 l0 = __float2bfloat16(v.x - __bfloat162float(h0));
    const __nv_bfloat16 l1 = __float2bfloat16(v.y - __bfloat162float(h1));
    const __nv_bfloat16 l2 = __float2bfloat16(v.z - __bfloat162float(h2));
    const __nv_bfloat16 l3 = __float2bfloat16(v.w - __bfloat162float(h3));
    *(uint2*)&g_A2[(size_t)row * 512 + c4 * 4] =
        make_uint2(pack_bf2(h0, h1), pack_bf2(h2, h3));
    *(uint2*)&g_A2[(size_t)row * 512 + 256 + c4 * 4] =
        make_uint2(pack_bf2(l0, l1), pack_bf2(l2, l3));
}

// ===========================================================================
// Kernel B: bf16 mma.sync GEMM with virtual K = 768 (hi*hi + lo*hi + hi*lo).
// BM=128, BN=128, BK=64; 8 warps, each 32(m) x 64(n); m16n8k16 fragments
// loaded as k-contiguous 32-bit pairs from padded smem (no ldmatrix).
// Epilogue fuses 1/denom and bm.
// ===========================================================================
#define GBM 128
#define GBN 128
#define GBK 64
#define ASTR 72     // 64 + 8 pad (bf16) -> conflict-free fragment LDS

__device__ __forceinline__ void mma_bf16(float* c, const u32* a, const u32* b) {
    asm volatile(
        "mma.sync.aligned.m16n8k16.row.col.f32.bf16.bf16.f32 "
        "{%0,%1,%2,%3}, {%4,%5,%6,%7}, {%8,%9}, {%0,%1,%2,%3};"
        : "+f"(c[0]), "+f"(c[1]), "+f"(c[2]), "+f"(c[3])
        : "r"(a[0]), "r"(a[1]), "r"(a[2]), "r"(a[3]), "r"(b[0]), "r"(b[1]));
}

__global__ void __launch_bounds__(256) mma_gemm_kernel(
    const float* __restrict__ bmv_,
    float* __restrict__ out,
    int S)
{
    __shared__ __nv_bfloat16 As[GBM][ASTR];
    __shared__ __nv_bfloat16 Bs[GBN][ASTR];

    const int t = threadIdx.x;
    const int lane = t & 31;
    const int w = t >> 5;
    const int warpM = w & 3;          // 0..3 -> m offset 32 each
    const int warpN = w >> 2;         // 0..1 -> n offset 64
    const int lr = lane >> 2;         // 0..7
    const int lc = lane & 3;          // 0..3

    const int rowBase = blockIdx.x * GBM;
    const int colBase = blockIdx.y * GBN;

    float c[2][8][4];
    #pragma unroll
    for (int i = 0; i < 2; i++)
        #pragma unroll
        for (int j = 0; j < 8; j++)
            #pragma unroll
            for (int q = 0; q < 4; q++) c[i][j][q] = 0.f;

    // virtual K chunks: ch 0..3: Ahi*Bhi; 4..7: Alo*Bhi; 8..11: Ahi*Blo
    for (int ch = 0; ch < 12; ch++) {
        const int acol = (ch < 8 ? ch : ch - 8) * GBK;               // col in g_A2 (hi|lo)
        const int bcol = (ch < 4 ? ch : (ch < 8 ? ch - 4 : ch - 8)) * GBK;
        const __nv_bfloat16* Bbuf = (ch < 8) ? g_Bhi : g_Blo;

        __syncthreads();   // previous chunk's fragment reads done
        #pragma unroll
        for (int i = 0; i < 4; i++) {
            const int id = t + i * 256;
            const int r  = id >> 3;
            const int k8 = (id & 7) * 8;
            uint4 v = make_uint4(0u, 0u, 0u, 0u);
            const int grow = rowBase + r;
            if (grow < S)
                v = *(const uint4*)&g_A2[(size_t)grow * 512 + acol + k8];
            *(uint4*)&As[r][k8] = v;
        }
        #pragma unroll
        for (int i = 0; i < 4; i++) {
            const int id = t + i * 256;
            const int r  = id >> 3;
            const int k8 = (id & 7) * 8;
            *(uint4*)&Bs[r][k8] =
                *(const uint4*)&Bbuf[(size_t)(colBase + r) * 256 + bcol + k8];
        }
        __syncthreads();

        #pragma unroll
        for (int kk = 0; kk < 4; kk++) {
            const int k0 = kk * 16;
            u32 a[2][4], b[8][2];
            #pragma unroll
            for (int i = 0; i < 2; i++) {
                const int m = warpM * 32 + i * 16 + lr;
                a[i][0] = *(const u32*)&As[m    ][k0 + lc * 2];
                a[i][1] = *(const u32*)&As[m + 8][k0 + lc * 2];
                a[i][2] = *(const u32*)&As[m    ][k0 + lc * 2 + 8];
                a[i][3] = *(const u32*)&As[m + 8][k0 + lc * 2 + 8];
            }
            #pragma unroll
            for (int j = 0; j < 8; j++) {
                const int n = warpN * 64 + j * 8 + lr;
                b[j][0] = *(const u32*)&Bs[n][k0 + lc * 2];
                b[j][1] = *(const u32*)&Bs[n][k0 + lc * 2 + 8];
            }
            #pragma unroll
            for (int i = 0; i < 2; i++)
                #pragma unroll
                for (int j = 0; j < 8; j++)
                    mma_bf16(c[i][j], a[i], b[j]);
        }
    }

    // epilogue: out = inv*acc + (denom*inv)*bm
    #pragma unroll
    for (int i = 0; i < 2; i++) {
        const int r0 = rowBase + warpM * 32 + i * 16 + lr;
        const int r1 = r0 + 8;
        float inv0 = 0.f, sg0 = 0.f, inv1 = 0.f, sg1 = 0.f;
        if (r0 < S) {
            const float d = g_denom[r0];
            inv0 = __fdividef(1.f, d + 1e-10f); sg0 = d * inv0;
        }
        if (r1 < S) {
            const float d = g_denom[r1];
            inv1 = __fdividef(1.f, d + 1e-10f); sg1 = d * inv1;
        }
        #pragma unroll
        for (int j = 0; j < 8; j++) {
            const int n = colBase + warpN * 64 + j * 8 + lc * 2;
            const float2 bm2 = *(const float2*)&bmv_[n];
            if (r0 < S) {
                float2 o;
                o.x = fmaf(c[i][j][0], inv0, sg0 * bm2.x);
                o.y = fmaf(c[i][j][1], inv0, sg0 * bm2.y);
                *(float2*)&out[(size_t)r0 * 256 + n] = o;
            }
            if (r1 < S) {
                float2 o;
                o.x = fmaf(c[i][j][2], inv1, sg1 * bm2.x);
                o.y = fmaf(c[i][j][3], inv1, sg1 * bm2.y);
                *(float2*)&out[(size_t)r1 * 256 + n] = o;
            }
        }
    }
}

// ===========================================================================
// inputs (metadata order): x, weights, Wg, bg, Wm, bm, p, index, [num_segments]
// ===========================================================================
extern "C" void kernel_launch(void* const* d_in, const int* in_sizes, int n_in,
                              void* d_out, int out_size) {
    const float* x       = (const float*)d_in[0];
    const float* weights = (const float*)d_in[1];
    const float* Wg      = (const float*)d_in[2];
    const float* bg      = (const float*)d_in[3];
    const float* Wm      = (const float*)d_in[4];
    const float* bm      = (const float*)d_in[5];
    const float* p       = (const float*)d_in[6];
    const int*   index   = (const int*)d_in[7];

    const int N = in_sizes[7];
    const int D = in_sizes[2];            // 256
    int S = out_size / D;                 // 20000
    if (S > S_MAX) S = S_MAX;

    prep_b_kernel<<<256, 256>>>(Wm);
    zero_kernel<<<(S_MAX * (D_FIX / 4) + 255) / 256, 256>>>();
    node_pool_kernel<<<(N + CHUNK - 1) / CHUNK, 256, POOL_SMEM>>>(
        x, weights, Wg, bg, p, index, N);
    convert_a_kernel<<<(S * 64 + 255) / 256, 256>>>(S);
    dim3 grid((S + GBM - 1) / GBM, D / GBN);
    mma_gemm_kernel<<<grid, 256>>>(bm, (float*)d_out, S);
}

// round 10
// speedup vs baseline: 2.0767x; 1.0651x over previous
#include <cuda_runtime.h>
#include <cuda_bf16.h>
#include <cstdint>
#include <math.h>

typedef unsigned int       u32;
typedef unsigned long long u64;

#define S_MAX 20000
#define S_PAD 20096          // S_MAX rounded up to 128
#define D_FIX 256
#define CHUNK 32
#define POOL_SMEM (CHUNK * 256 * 4 + CHUNK * 4 + (CHUNK + 1) * 4)

// Scratch (device globals: allocation-free per harness rules)
__device__ float g_pooled[S_MAX * D_FIX];       // raw Σ e_i x_i  [S,256]
__device__ float g_denom[S_MAX];                // raw Σ e_i      [S]
__device__ __nv_bfloat16 g_A2[S_PAD * 512];     // pooled bf16: [s][0:256)=hi, [256:512)=lo
__device__ __nv_bfloat16 g_Bhi[256 * 256];      // Wm^T hi  [n][k]
__device__ __nv_bfloat16 g_Blo[256 * 256];      // Wm^T lo  [n][k]

// single dynamic-smem symbol shared by all kernels in this TU
extern __shared__ char dyn_smem[];

__device__ __forceinline__ u32 smem_u32(const void* p) {
    u32 a;
    asm("{ .reg .u64 t; cvta.to.shared.u64 t, %1; cvt.u32.u64 %0, t; }" : "=r"(a) : "l"(p));
    return a;
}
__device__ __forceinline__ u32 pack_bf2(__nv_bfloat16 a, __nv_bfloat16 b) {
    return (u32)__bfloat16_as_ushort(a) | ((u32)__bfloat16_as_ushort(b) << 16);
}
__device__ __forceinline__ void cpasync16(u32 dst, const void* src) {
    asm volatile("cp.async.cg.shared.global [%0], [%1], 16;"
                 :: "r"(dst), "l"(src) : "memory");
}
__device__ __forceinline__ void ldsm4(u32* r, u32 addr) {
    asm volatile("ldmatrix.sync.aligned.m8n8.x4.shared.b16 {%0,%1,%2,%3}, [%4];"
                 : "=r"(r[0]), "=r"(r[1]), "=r"(r[2]), "=r"(r[3]) : "r"(addr));
}
__device__ __forceinline__ void mma_bf16(float* c, const u32* a, const u32* b) {
    asm volatile(
        "mma.sync.aligned.m16n8k16.row.col.f32.bf16.bf16.f32 "
        "{%0,%1,%2,%3}, {%4,%5,%6,%7}, {%8,%9}, {%0,%1,%2,%3};"
        : "+f"(c[0]), "+f"(c[1]), "+f"(c[2]), "+f"(c[3])
        : "r"(a[0]), "r"(a[1]), "r"(a[2]), "r"(a[3]), "r"(b[0]), "r"(b[1]));
}

// ===========================================================================
// Kernel Z: zero the accumulators
// ===========================================================================
__global__ void __launch_bounds__(256) zero_kernel() {
    const int i = blockIdx.x * 256 + threadIdx.x;
    const float4 z = make_float4(0.f, 0.f, 0.f, 0.f);
    if (i < S_MAX * (D_FIX / 4)) ((float4*)g_pooled)[i] = z;
    if (i < S_MAX / 4)           ((float4*)g_denom)[i]  = z;
}

// ===========================================================================
// Kernel P: split Wm^T into bf16 hi/lo  ([n][k], K-contiguous)
// ===========================================================================
__global__ void __launch_bounds__(256) prep_b_kernel(const float* __restrict__ Wm) {
    const int n = blockIdx.x;
    const int k = threadIdx.x;
    const float v = Wm[k * 256 + n];
    const __nv_bfloat16 hi = __float2bfloat16(v);
    const __nv_bfloat16 lo = __float2bfloat16(v - __bfloat162float(hi));
    g_Bhi[n * 256 + k] = hi;
    g_Blo[n * 256 + k] = lo;
}

// ===========================================================================
// Kernel A: node-parallel fused gate + weighted pooling.
// Denominator flush is now warp-parallel atomics (no serial t==0 tail).
// ===========================================================================
__global__ void __launch_bounds__(256) node_pool_kernel(
    const float* __restrict__ x,
    const float* __restrict__ weights,
    const float* __restrict__ Wg,
    const float* __restrict__ bg,
    const float* __restrict__ p_,
    const int*   __restrict__ index,
    int N)
{
    float* xs  = (float*)dyn_smem;
    float* es  = xs + CHUNK * 256;
    int*   idxs = (int*)(es + CHUNK);

    const int base = blockIdx.x * CHUNK;
    const int len  = min(CHUNK, N - base);
    const int t = threadIdx.x;
    const int w = t >> 5;
    const int l = t & 31;

    if (t < len) idxs[t] = index[base + t];
    if (t == 0)  idxs[len] = -1;

    {
        const float4* src = (const float4*)x + (size_t)base * 64;
        float4* dst = (float4*)xs;
        const int n4 = len * 64;
        #pragma unroll 8
        for (int i = t; i < n4; i += 256) dst[i] = __ldcs(src + i);
    }
    __syncthreads();

    const float4* Wg4 = (const float4*)Wg;
    const float4 wga = Wg4[l];
    const float4 wgb = Wg4[32 + l];
    const float bgv = bg[0];
    const float pv  = p_[0];

    const int NJJ = CHUNK / 8;
    float pdv[NJJ], wv[NJJ];
    const float4* xs4 = (const float4*)xs;
    #pragma unroll
    for (int jj = 0; jj < NJJ; jj++) {
        const int j = w + jj * 8;
        pdv[jj] = 0.f; wv[jj] = 1.f;
        if (j < len) {
            const float4 xa = xs4[j * 64 + l];
            const float4 xb = xs4[j * 64 + 32 + l];
            pdv[jj] = xa.x * wga.x + xa.y * wga.y + xa.z * wga.z + xa.w * wga.w
                    + xb.x * wgb.x + xb.y * wgb.y + xb.z * wgb.z + xb.w * wgb.w;
            wv[jj] = __ldg(&weights[base + j]);
        }
    }
    #pragma unroll
    for (int jj = 0; jj < NJJ; jj++) {
        float pd = pdv[jj];
        #pragma unroll
        for (int off = 16; off; off >>= 1)
            pd += __shfl_xor_sync(0xffffffffu, pd, off);
        pdv[jj] = pd;
    }
    #pragma unroll
    for (int jj = 0; jj < NJJ; jj++) {
        const int j = w + jj * 8;
        if (j < len && l == 0)
            es[j] = expf(fmaf(pv, logf(wv[jj]), pdv[jj] + bgv));
    }
    __syncthreads();

    // denominators: one atomic per node, warp-parallel (t < len <= 32)
    if (t < len) atomicAdd(&g_denom[idxs[t]], es[t]);

    // thread-per-dim weighted accumulation + boundary flush
    {
        float acc = 0.f;
        int cur = idxs[0];
        for (int j = 0; j < len; j++) {
            acc = fmaf(es[j], xs[j * 256 + t], acc);
            const int nxt = idxs[j + 1];
            if (nxt != cur) {
                atomicAdd(&g_pooled[(size_t)cur * 256 + t], acc);
                acc = 0.f;
                cur = nxt;
            }
        }
    }
}

// ===========================================================================
// Kernel C: convert pooled fp32 -> bf16 hi|lo; zero-fill padded rows
// ===========================================================================
__global__ void __launch_bounds__(256) convert_a_kernel(int S) {
    const int idx = blockIdx.x * 256 + threadIdx.x;   // over S_PAD*64 float4
    if (idx >= S_PAD * 64) return;
    const int row = idx >> 6;
    const int c4  = idx & 63;
    float4 v = make_float4(0.f, 0.f, 0.f, 0.f);
    if (row < S) v = ((const float4*)g_pooled)[idx];
    const __nv_bfloat16 h0 = __float2bfloat16(v.x);
    const __nv_bfloat16 h1 = __float2bfloat16(v.y);
    const __nv_bfloat16 h2 = __float2bfloat16(v.z);
    const __nv_bfloat16 h3 = __float2bfloat16(v.w);
    const __nv_bfloat16 l0 = __float2bfloat16(v.x - __bfloat162float(h0));
    const __nv_bfloat16 l1 = __float2bfloat16(v.y - __bfloat162float(h1));
    const __nv_bfloat16 l2 = __float2bfloat16(v.z - __bfloat162float(h2));
    const __nv_bfloat16 l3 = __float2bfloat16(v.w - __bfloat162float(h3));
    *(uint2*)&g_A2[(size_t)row * 512 + c4 * 4] =
        make_uint2(pack_bf2(h0, h1), pack_bf2(h2, h3));
    *(uint2*)&g_A2[(size_t)row * 512 + 256 + c4 * 4] =
        make_uint2(pack_bf2(l0, l1), pack_bf2(l2, l3));
}

// ===========================================================================
// Kernel B: bf16 mma.sync GEMM, virtual K = 768 (hi*hi + lo*hi + hi*lo).
// BM=128, BN=128, BK=64; cp.async double-buffered smem; ldmatrix fragments.
// 8 warps, each 32(m) x 64(n). Epilogue fuses 1/denom and bm.
// ===========================================================================
#define GBM 128
#define GBN 128
#define GBK 64
#define ASTR 72                       // bf16 row stride (64 + 8 pad)
#define TBYTES (128 * ASTR * 2)       // 18432 B per tile buffer
#define GEMM_SMEM (4 * TBYTES)        // A0,A1,B0,B1 = 73728 B

__global__ void __launch_bounds__(256, 2) mma_gemm_kernel(
    const float* __restrict__ bmv_,
    float* __restrict__ out,
    int S)
{
    const u32 sbase = smem_u32(dyn_smem);
    const int t = threadIdx.x;
    const int lane = t & 31;
    const int w = t >> 5;
    const int warpM = w & 3;
    const int warpN = w >> 2;
    const int lr = lane >> 2;
    const int lc = lane & 3;
    const int q  = lane >> 3;         // ldmatrix matrix id for this lane
    const int mr = lane & 7;          // row within matrix

    // per-lane ldmatrix offsets
    const int aro = (q & 1) * 8 + mr; // A: matrices 0/1 = row blocks, 2/3 = k+8
    const int ako = (q >> 1) * 8;
    const int bro = (q >> 1) * 8 + mr;// B: matrices 0/1 = k blocks, 2/3 = n+8
    const int bko = (q & 1) * 8;

    const int rowBase = blockIdx.x * GBM;
    const int colBase = blockIdx.y * GBN;

    // staging coordinates (per thread: 4 A lines + 4 B lines of 16B)
    const int sr = t >> 3;            // +64 per i-step? no: id = t + i*256
    const int sk8 = (t & 7) * 8;

    float c[2][8][4];
    #pragma unroll
    for (int i = 0; i < 2; i++)
        #pragma unroll
        for (int j = 0; j < 8; j++)
            #pragma unroll
            for (int qq = 0; qq < 4; qq++) c[i][j][qq] = 0.f;

    // stage chunk ch into buffer buf (A: g_A2, B: g_Bhi/g_Blo), then commit
    auto stage = [&](int ch, int buf) {
        const int kc = ch & 3;
        const int acol = kc * 64 + ((ch >= 4 && ch < 8) ? 256 : 0);
        const __nv_bfloat16* Bb = (ch < 8) ? g_Bhi : g_Blo;
        const u32 abase = sbase + buf * TBYTES;
        const u32 bbase = sbase + 2 * TBYTES + buf * TBYTES;
        #pragma unroll
        for (int i = 0; i < 4; i++) {
            const int r = sr + i * 32;
            cpasync16(abase + r * (ASTR * 2) + sk8 * 2,
                      &g_A2[(size_t)(rowBase + r) * 512 + acol + sk8]);
            cpasync16(bbase + r * (ASTR * 2) + sk8 * 2,
                      &Bb[(size_t)(colBase + r) * 256 + kc * 64 + sk8]);
        }
        asm volatile("cp.async.commit_group;" ::: "memory");
    };

    stage(0, 0);

    for (int ch = 0; ch < 12; ch++) {
        const int buf = ch & 1;
        if (ch + 1 < 12) {
            stage(ch + 1, buf ^ 1);
            asm volatile("cp.async.wait_group 1;" ::: "memory");
        } else {
            asm volatile("cp.async.wait_group 0;" ::: "memory");
        }
        __syncthreads();

        const u32 abase = sbase + buf * TBYTES;
        const u32 bbase = sbase + 2 * TBYTES + buf * TBYTES;
        #pragma unroll
        for (int kk = 0; kk < 4; kk++) {
            const int k0 = kk * 16;
            u32 a[2][4], b[4][4];
            #pragma unroll
            for (int i = 0; i < 2; i++)
                ldsm4(a[i], abase + (warpM * 32 + i * 16 + aro) * (ASTR * 2)
                                  + (k0 + ako) * 2);
            #pragma unroll
            for (int jp = 0; jp < 4; jp++)
                ldsm4(b[jp], bbase + (warpN * 64 + jp * 16 + bro) * (ASTR * 2)
                                   + (k0 + bko) * 2);
            #pragma unroll
            for (int i = 0; i < 2; i++)
                #pragma unroll
                for (int jp = 0; jp < 4; jp++) {
                    mma_bf16(c[i][2 * jp],     a[i], &b[jp][0]);
                    mma_bf16(c[i][2 * jp + 1], a[i], &b[jp][2]);
                }
        }
        __syncthreads();
    }

    // epilogue: out = inv*acc + (denom*inv)*bm
    #pragma unroll
    for (int i = 0; i < 2; i++) {
        const int r0 = rowBase + warpM * 32 + i * 16 + lr;
        const int r1 = r0 + 8;
        float inv0 = 0.f, sg0 = 0.f, inv1 = 0.f, sg1 = 0.f;
        if (r0 < S) {
            const float d = g_denom[r0];
            inv0 = __fdividef(1.f, d + 1e-10f); sg0 = d * inv0;
        }
        if (r1 < S) {
            const float d = g_denom[r1];
            inv1 = __fdividef(1.f, d + 1e-10f); sg1 = d * inv1;
        }
        #pragma unroll
        for (int j = 0; j < 8; j++) {
            const int n = colBase + warpN * 64 + j * 8 + lc * 2;
            const float2 bm2 = *(const float2*)&bmv_[n];
            if (r0 < S) {
                float2 o;
                o.x = fmaf(c[i][j][0], inv0, sg0 * bm2.x);
                o.y = fmaf(c[i][j][1], inv0, sg0 * bm2.y);
                *(float2*)&out[(size_t)r0 * 256 + n] = o;
            }
            if (r1 < S) {
                float2 o;
                o.x = fmaf(c[i][j][2], inv1, sg1 * bm2.x);
                o.y = fmaf(c[i][j][3], inv1, sg1 * bm2.y);
                *(float2*)&out[(size_t)r1 * 256 + n] = o;
            }
        }
    }
}

// ===========================================================================
// inputs (metadata order): x, weights, Wg, bg, Wm, bm, p, index, [num_segments]
// ===========================================================================
extern "C" void kernel_launch(void* const* d_in, const int* in_sizes, int n_in,
                              void* d_out, int out_size) {
    const float* x       = (const float*)d_in[0];
    const float* weights = (const float*)d_in[1];
    const float* Wg      = (const float*)d_in[2];
    const float* bg      = (const float*)d_in[3];
    const float* Wm      = (const float*)d_in[4];
    const float* bm      = (const float*)d_in[5];
    const float* p       = (const float*)d_in[6];
    const int*   index   = (const int*)d_in[7];

    const int N = in_sizes[7];
    const int D = in_sizes[2];            // 256
    int S = out_size / D;                 // 20000
    if (S > S_MAX) S = S_MAX;

    cudaFuncSetAttribute(mma_gemm_kernel,
                         cudaFuncAttributeMaxDynamicSharedMemorySize, GEMM_SMEM);

    prep_b_kernel<<<256, 256>>>(Wm);
    zero_kernel<<<(S_MAX * (D_FIX / 4) + 255) / 256, 256>>>();
    node_pool_kernel<<<(N + CHUNK - 1) / CHUNK, 256, POOL_SMEM>>>(
        x, weights, Wg, bg, p, index, N);
    convert_a_kernel<<<(S_PAD * 64 + 255) / 256, 256>>>(S);
    dim3 grid((S + GBM - 1) / GBM, D / GBN);
    mma_gemm_kernel<<<grid, 256, GEMM_SMEM>>>(bm, (float*)d_out, S);
}